// round 15
// baseline (speedup 1.0000x reference)
#include <cuda_runtime.h>
#include <cstdint>

// TokenBladeBank: FNV-1a 4-gram hash -> gather from 8 blade banks.
// token_window: (8, 8192, 4) int32 OR int64 (detected in-warp)
// bank:         (8, 500000, 16) float32
// out:          (8, 8192, 8, 16) float32  ->  out[pos*128 + blade*16 + d]
//
// R10 structure (best) with PLAIN WRITE-BACK stores. Every kernel since R2
// used streaming/write-through stores, forcing 32 MB of DRAM write traffic
// per graph replay. But the full steady-state working set (touched bank
// lines ~31-35 MB + tokens 2 MB + output 32 MB ~ 70 MB) fits in the 126 MB
// L2, and each replay overwrites the SAME output lines: with default
// write-back policy those lines stay dirty-resident and produce no DRAM
// write traffic at all in steady state. Full-line 512 B coalesced warp
// stores avoid fetch-on-write. Gather structure unchanged: 8 pos/warp,
// width-8 shuffle-shared hashing, 8 independent float4 __ldg gathers
// (4 lanes cover one 64 B row = 2 full sectors), 128-thread blocks.

#define TBB_N_SLOTS    500000u
#define TBB_FNV_OFFSET 2166136261u
#define TBB_FNV_PRIME  16777619u
#define TBB_POS_PER_WARP 8

__device__ __forceinline__ unsigned tbb_fnv4(unsigned a, unsigned b,
                                             unsigned c, unsigned d)
{
    unsigned h = TBB_FNV_OFFSET;
    h = (h ^ a) * TBB_FNV_PRIME;
    h = (h ^ b) * TBB_FNV_PRIME;
    h = (h ^ c) * TBB_FNV_PRIME;
    h = (h ^ d) * TBB_FNV_PRIME;
    return h % TBB_N_SLOTS;
}

__global__ void __launch_bounds__(128)
tbb_gather_kernel(const unsigned* __restrict__ tw,
                  const float4*  __restrict__ bank,
                  float4*        __restrict__ out,
                  int n_pos)
{
    const int t    = blockIdx.x * blockDim.x + threadIdx.x;
    const int warp = t >> 5;
    const int lane = t & 31;
    const int pos0 = warp * TBB_POS_PER_WARP;
    if (pos0 >= n_pos) return;

    // In-warp dtype detection: odd 32-bit words of the first 64 token words.
    // int64 little-endian layout => all zero high-halves (tokens < 50257);
    // int32 layout => random tokens, P(all 32 == 0) ~ 50257^-32 ~ 0.
    const unsigned probe = __ldg(&tw[2 * lane + 1]);
    const unsigned nz    = __ballot_sync(0xffffffffu, probe != 0u);
    const int stride     = (nz == 0u) ? 2 : 1;

    const unsigned blade = (unsigned)lane >> 2;   // 0..7
    const unsigned q     = (unsigned)lane & 3;    // float4 within 16-fp row
    const int      sub   = lane & 7;              // which position I hash

    const uint4* tw4 = (const uint4*)tw;

    // Each lane hashes ONE position (pos0+sub); width-8 shuffles broadcast
    // all 8 addresses to every lane.
    unsigned myaddr;
    if (stride == 1) {
        uint4 tk = __ldg(&tw4[pos0 + sub]);
        myaddr = tbb_fnv4(tk.x, tk.y, tk.z, tk.w);
    } else {
        const size_t p = (size_t)(pos0 + sub) * 2;
        uint4 ta = __ldg(&tw4[p]);
        uint4 tb = __ldg(&tw4[p + 1]);
        myaddr = tbb_fnv4(ta.x, ta.z, tb.x, tb.z);
    }

    unsigned addr[TBB_POS_PER_WARP];
    #pragma unroll
    for (int g = 0; g < TBB_POS_PER_WARP; g++)
        addr[g] = __shfl_sync(0xffffffffu, myaddr, g, 8);

    // 8 independent random 16 B gathers (MLP=8).
    // Lanes 4b..4b+3 cover one contiguous 64 B row: perfect sector use.
    float4 v[TBB_POS_PER_WARP];
    #pragma unroll
    for (int g = 0; g < TBB_POS_PER_WARP; g++) {
        const size_t bidx =
            ((size_t)blade * TBB_N_SLOTS + (size_t)addr[g]) * 4 + q;
        v[g] = __ldg(&bank[bidx]);
    }

    // 8 coalesced 512 B PLAIN write-back stores -> 4 KB contiguous per warp.
    // Dirty lines stay L2-resident across replays: no steady-state DRAM
    // write traffic.
    #pragma unroll
    for (int g = 0; g < TBB_POS_PER_WARP; g++)
        out[(size_t)(pos0 + g) * 32 + lane] = v[g];
}

extern "C" void kernel_launch(void* const* d_in, const int* in_sizes, int n_in,
                              void* d_out, int out_size)
{
    const unsigned* tw   = (const unsigned*)d_in[0];
    const float4*   bank = (const float4*)d_in[1];
    float4*         out  = (float4*)d_out;

    const int n_pos = out_size / 128;             // 65536 positions (dtype-proof)

    const int threads = 128;
    const int warps   = (n_pos + TBB_POS_PER_WARP - 1) / TBB_POS_PER_WARP;
    const int blocks  = (warps * 32 + threads - 1) / threads;  // 2048
    tbb_gather_kernel<<<blocks, threads>>>(tw, bank, out, n_pos);
}

// round 16
// speedup vs baseline: 1.0025x; 1.0025x over previous
#include <cuda_runtime.h>
#include <cstdint>

// TokenBladeBank: FNV-1a 4-gram hash -> gather from 8 blade banks.
// token_window: (8, 8192, 4) int32 OR int64 (detected in-warp)
// bank:         (8, 500000, 16) float32
// out:          (8, 8192, 8, 16) float32  ->  out[pos*128 + blade*16 + d]
//
// R14 structure with EVICT_LAST STORES — the one untested cell of the
// cache-policy matrix. The 32 MB output is the ideal L2 pinning target:
// deterministic addresses, overwritten every graph replay, never read.
// If output lines stay dirty-resident, steady-state DRAM write traffic
// drops to ~0 (each replay re-dirties resident lines) and DRAM carries
// only the random read misses. Loads stay plain __ldg (load-side pinning
// regressed in R4/R7/R8). Gather structure unchanged (local optimum):
// 8 pos/warp, width-8 shuffle-shared hashing, 8 independent float4 __ldg
// gathers (4 lanes cover one 64 B row = 2 full sectors), 128-thr blocks.

#define TBB_N_SLOTS    500000u
#define TBB_FNV_OFFSET 2166136261u
#define TBB_FNV_PRIME  16777619u
#define TBB_POS_PER_WARP 8

__device__ __forceinline__ unsigned tbb_fnv4(unsigned a, unsigned b,
                                             unsigned c, unsigned d)
{
    unsigned h = TBB_FNV_OFFSET;
    h = (h ^ a) * TBB_FNV_PRIME;
    h = (h ^ b) * TBB_FNV_PRIME;
    h = (h ^ c) * TBB_FNV_PRIME;
    h = (h ^ d) * TBB_FNV_PRIME;
    return h % TBB_N_SLOTS;
}

__device__ __forceinline__ unsigned long long pol_evict_last()
{
    unsigned long long p;
    asm("createpolicy.fractional.L2::evict_last.b64 %0, 1.0;" : "=l"(p));
    return p;
}

__device__ __forceinline__ void stg_pin_f4(float4* a, float4 v,
                                           unsigned long long pol)
{
    asm volatile("st.global.L2::cache_hint.v4.f32 [%0], {%1,%2,%3,%4}, %5;"
                 :: "l"(a), "f"(v.x), "f"(v.y), "f"(v.z), "f"(v.w), "l"(pol)
                 : "memory");
}

__global__ void __launch_bounds__(128)
tbb_gather_kernel(const unsigned* __restrict__ tw,
                  const float4*  __restrict__ bank,
                  float4*        __restrict__ out,
                  int n_pos)
{
    const int t    = blockIdx.x * blockDim.x + threadIdx.x;
    const int warp = t >> 5;
    const int lane = t & 31;
    const int pos0 = warp * TBB_POS_PER_WARP;
    if (pos0 >= n_pos) return;

    // In-warp dtype detection: odd 32-bit words of the first 64 token words.
    // int64 little-endian layout => all zero high-halves (tokens < 50257);
    // int32 layout => random tokens, P(all 32 == 0) ~ 50257^-32 ~ 0.
    const unsigned probe = __ldg(&tw[2 * lane + 1]);
    const unsigned nz    = __ballot_sync(0xffffffffu, probe != 0u);
    const int stride     = (nz == 0u) ? 2 : 1;

    const unsigned blade = (unsigned)lane >> 2;   // 0..7
    const unsigned q     = (unsigned)lane & 3;    // float4 within 16-fp row
    const int      sub   = lane & 7;              // which position I hash

    const unsigned long long pl = pol_evict_last();

    const uint4* tw4 = (const uint4*)tw;

    // Each lane hashes ONE position (pos0+sub); width-8 shuffles broadcast
    // all 8 addresses to every lane.
    unsigned myaddr;
    if (stride == 1) {
        uint4 tk = __ldg(&tw4[pos0 + sub]);
        myaddr = tbb_fnv4(tk.x, tk.y, tk.z, tk.w);
    } else {
        const size_t p = (size_t)(pos0 + sub) * 2;
        uint4 ta = __ldg(&tw4[p]);
        uint4 tb = __ldg(&tw4[p + 1]);
        myaddr = tbb_fnv4(ta.x, ta.z, tb.x, tb.z);
    }

    unsigned addr[TBB_POS_PER_WARP];
    #pragma unroll
    for (int g = 0; g < TBB_POS_PER_WARP; g++)
        addr[g] = __shfl_sync(0xffffffffu, myaddr, g, 8);

    // 8 independent random 16 B gathers (MLP=8).
    // Lanes 4b..4b+3 cover one contiguous 64 B row: perfect sector use.
    float4 v[TBB_POS_PER_WARP];
    #pragma unroll
    for (int g = 0; g < TBB_POS_PER_WARP; g++) {
        const size_t bidx =
            ((size_t)blade * TBB_N_SLOTS + (size_t)addr[g]) * 4 + q;
        v[g] = __ldg(&bank[bidx]);
    }

    // 8 coalesced 512 B stores pinned L2-resident (evict_last): across graph
    // replays the same lines are re-dirtied in place -> ~0 DRAM write traffic.
    #pragma unroll
    for (int g = 0; g < TBB_POS_PER_WARP; g++)
        stg_pin_f4(&out[(size_t)(pos0 + g) * 32 + lane], v[g], pl);
}

extern "C" void kernel_launch(void* const* d_in, const int* in_sizes, int n_in,
                              void* d_out, int out_size)
{
    const unsigned* tw   = (const unsigned*)d_in[0];
    const float4*   bank = (const float4*)d_in[1];
    float4*         out  = (float4*)d_out;

    const int n_pos = out_size / 128;             // 65536 positions (dtype-proof)

    const int threads = 128;
    const int warps   = (n_pos + TBB_POS_PER_WARP - 1) / TBB_POS_PER_WARP;
    const int blocks  = (warps * 32 + threads - 1) / threads;  // 2048
    tbb_gather_kernel<<<blocks, threads>>>(tw, bank, out, n_pos);
}